// round 7
// baseline (speedup 1.0000x reference)
#include <cuda_runtime.h>
#include <cstdint>

#define WDIM 1024
#define NPIX (WDIM * WDIM)
#define HALF (NPIX / 2)

// ---- constant-bank weights (written by prep kernel; read via the dedicated LDC port) ----
// CW1[(c*9+j)*8 + k] : 16B = w1t[cj][4k..4k+3]  (w1t[cj][o] = w1[o][cj]); only k<4 used by main
// CW2[o*4 + i]       : 16B = w2t[o][4i..4i+3]   (w2t[o][m] = w2[m][o], m>=13 -> 0); only i<2 used
__constant__ __align__(16) ulonglong2 CW1[54 * 8];
__constant__ __align__(16) ulonglong2 CW2[32 * 4];
__constant__ __align__(16) unsigned long long CB1[16];
__constant__ __align__(16) unsigned long long CB2[7];

static __device__ __forceinline__ unsigned long long pack2(float a, float b) {
    unsigned long long r;
    asm("mov.b64 %0, {%1,%2};" : "=l"(r) : "f"(a), "f"(b));
    return r;
}
static __device__ __forceinline__ void fma2(unsigned long long& d, unsigned long long a, unsigned long long b) {
    asm("fma.rn.f32x2 %0, %1, %2, %0;" : "+l"(d) : "l"(a), "l"(b));
}
static __device__ __forceinline__ float2 unpack2(unsigned long long v) {
    float2 r;
    asm("mov.b64 {%0,%1}, %2;" : "=f"(r.x), "=f"(r.y) : "l"(v));
    return r;
}

// Prep: transpose/pack weights into the constant bank via its global alias.
__global__ void prep_kernel(const float* __restrict__ w1, const float* __restrict__ b1,
                            const float* __restrict__ w2, const float* __restrict__ b2,
                            float* __restrict__ cw1, float* __restrict__ cw2,
                            float* __restrict__ cb1, float* __restrict__ cb2)
{
    const int tid = threadIdx.x;
    for (int i = tid; i < 54 * 32; i += 256) {
        int cj = i >> 5, o = i & 31;
        cw1[i] = w1[o * 54 + cj];
    }
    for (int i = tid; i < 32 * 16; i += 256) {
        int o = i >> 4, m = i & 15;
        cw2[i] = (m < 13) ? w2[m * 32 + o] : 0.0f;
    }
    if (tid < 32) cb1[tid] = b1[tid];
    if (tid < 14) cb2[tid] = (tid < 13) ? b2[tid] : 0.0f;
}

// softmax(9) + inverse rotation (register selects) + tanh + sigmoid; coalesced stores.
static __device__ __forceinline__ void epilogue(const float* z, int d, int p,
                                                float* __restrict__ out)
{
    const int rb0 = d & 1;
    const int rb1 = (d >> 1) & 1;

    float mx = z[0];
#pragma unroll
    for (int j = 1; j < 9; j++) mx = fmaxf(mx, z[j]);
    float s[9];
    float sum = 0.0f;
#pragma unroll
    for (int j = 0; j < 9; j++) { s[j] = __expf(z[j] - mx); sum += s[j]; }
    float inv = __fdividef(1.0f, sum);

    const int I0[9] = {0,1,2,3,4,5,6,7,8};
    const int I1[9] = {2,5,8,1,4,7,0,3,6};
    const int I2[9] = {8,7,6,5,4,3,2,1,0};
    const int I3[9] = {6,3,0,7,4,1,8,5,2};
#pragma unroll
    for (int m = 0; m < 9; m++) {
        float v01 = rb0 ? s[I1[m]] : s[I0[m]];
        float v23 = rb0 ? s[I3[m]] : s[I2[m]];
        float v = rb1 ? v23 : v01;
        out[m * NPIX + p] = v * inv;
    }
    out[9 * NPIX + p] = tanhf(z[9]);
#pragma unroll
    for (int m = 0; m < 3; m++)
        out[(10 + m) * NPIX + p] = __fdividef(1.0f, 1.0f + __expf(-z[10 + m]));
}

__global__ void __launch_bounds__(256, 2) energy_cnn_kernel(
    const float* __restrict__ se, const float* __restrict__ te,
    const float* __restrict__ sr, const float* __restrict__ hc,
    const float* __restrict__ rot, const float* __restrict__ w1,
    const float* __restrict__ w2, float* __restrict__ out)
{
    // smem halves: layer-1 channels 16..31 and layer-2 output pairs 4..6(+pad)
    __shared__ __align__(16) float w1sh[54 * 16];  // w1sh[cj*16 + oo] = w1[(16+oo)*54 + cj]
    __shared__ __align__(16) float w2sh[32 * 8];   // w2sh[o*8 + t] = w2[(8+t)*32 + o] (t+8<13 else 0)

    const int tid = threadIdx.x;
    for (int i = tid; i < 54 * 16; i += 256) {
        int cj = i >> 4, oo = i & 15;
        w1sh[i] = w1[(16 + oo) * 54 + cj];
    }
    for (int i = tid; i < 32 * 8; i += 256) {
        int o = i >> 3, t = i & 7;
        w2sh[i] = (8 + t < 13) ? w2[(8 + t) * 32 + o] : 0.0f;
    }
    __syncthreads();

    // Two pixels per thread: p0 top half, p1 = p0 + HALF.
    const int p0 = blockIdx.x * 256 + tid;
    const int p1 = p0 + HALF;
    const int x0 = p0 & (WDIM - 1), y0 = p0 >> 10;
    const int x1 = x0,              y1 = y0 + (WDIM / 2);

    const float TP = 6.2831853071795864f;
    int d0, d1;
    {
        float t = rot[p0] / TP * 4.0f;  d0 = ((int)t) & 3;
        float u = rot[p1] / TP * 4.0f;  d1 = ((int)u) & 3;
    }

    // Rotated gather addresses (rotation = address permutation).
    int idx0[9], idx1[9];
    {
        const int rb00 = d0 & 1, rb01 = (d0 >> 1) & 1;
        const int rb10 = d1 & 1, rb11 = (d1 >> 1) & 1;
#pragma unroll
        for (int j = 0; j < 9; j++) {
            const int dy0 = j / 3 - 1, dx0 = j % 3 - 1;
            {
                int ay = rb01 ? -dy0 : dy0;
                int ax = rb01 ? -dx0 : dx0;
                int dy = rb00 ? -ax : ay;
                int dx = rb00 ? ay : ax;
                idx0[j] = (((y0 + dy) & (WDIM - 1)) << 10) + ((x0 + dx) & (WDIM - 1));
            }
            {
                int ay = rb11 ? -dy0 : dy0;
                int ax = rb11 ? -dx0 : dx0;
                int dy = rb10 ? -ax : ay;
                int dx = rb10 ? ay : ax;
                idx1[j] = (((y1 + dy) & (WDIM - 1)) << 10) + ((x1 + dx) & (WDIM - 1));
            }
        }
    }

    // ---- layer 1: 54 -> 32; channels 0-15 via constant port, 16-31 via smem port ----
    unsigned long long acc0[16], acc1[16];
#pragma unroll
    for (int i = 0; i < 16; i++) {
        unsigned long long b = CB1[i];
        acc0[i] = b; acc1[i] = b;
    }

    const float* chans[6] = { se, te, sr, hc, hc + NPIX, hc + 2 * NPIX };
#pragma unroll
    for (int c = 0; c < 6; c++) {
        const float* __restrict__ ch = chans[c];
#pragma unroll
        for (int j = 0; j < 9; j++) {
            float a0 = __ldg(&ch[idx0[j]]);
            float a1 = __ldg(&ch[idx1[j]]);
            unsigned long long aa0 = pack2(a0, a0);
            unsigned long long aa1 = pack2(a1, a1);
            const ulonglong2* __restrict__ wrow =
                (const ulonglong2*)&w1sh[(c * 9 + j) * 16];
#pragma unroll
            for (int k = 0; k < 4; k++) {
                ulonglong2 wc = CW1[(c * 9 + j) * 8 + k];   // LDC.128 (constant port)
                ulonglong2 ws = wrow[k];                    // LDS.128 (smem port)
                fma2(acc0[2 * k],     aa0, wc.x);
                fma2(acc0[2 * k + 1], aa0, wc.y);
                fma2(acc1[2 * k],     aa1, wc.x);
                fma2(acc1[2 * k + 1], aa1, wc.y);
                fma2(acc0[8 + 2 * k],     aa0, ws.x);
                fma2(acc0[8 + 2 * k + 1], aa0, ws.y);
                fma2(acc1[8 + 2 * k],     aa1, ws.x);
                fma2(acc1[8 + 2 * k + 1], aa1, ws.y);
            }
        }
    }

    float h0[32], h1[32];
#pragma unroll
    for (int i = 0; i < 16; i++) {
        float2 v0 = unpack2(acc0[i]);
        float2 v1 = unpack2(acc1[i]);
        h0[2 * i]     = fmaxf(v0.x, 0.0f);
        h0[2 * i + 1] = fmaxf(v0.y, 0.0f);
        h1[2 * i]     = fmaxf(v1.x, 0.0f);
        h1[2 * i + 1] = fmaxf(v1.y, 0.0f);
    }

    // ---- layer 2: 32 -> 13; pairs 0-3 via constant, pairs 4-6 via smem ----
    unsigned long long x20[7], x21[7];
#pragma unroll
    for (int m = 0; m < 7; m++) {
        unsigned long long b = CB2[m];
        x20[m] = b; x21[m] = b;
    }
#pragma unroll
    for (int o = 0; o < 32; o++) {
        unsigned long long hh0 = pack2(h0[o], h0[o]);
        unsigned long long hh1 = pack2(h1[o], h1[o]);
        ulonglong2 wc0 = CW2[o * 4 + 0];                        // pairs 0,1 (LDC)
        ulonglong2 wc1 = CW2[o * 4 + 1];                        // pairs 2,3 (LDC)
        const ulonglong2* __restrict__ ws = (const ulonglong2*)&w2sh[o * 8];
        ulonglong2 ws0 = ws[0];                                 // pairs 4,5 (LDS)
        ulonglong2 ws1 = ws[1];                                 // pair  6 + pad (LDS)
        fma2(x20[0], hh0, wc0.x);  fma2(x21[0], hh1, wc0.x);
        fma2(x20[1], hh0, wc0.y);  fma2(x21[1], hh1, wc0.y);
        fma2(x20[2], hh0, wc1.x);  fma2(x21[2], hh1, wc1.x);
        fma2(x20[3], hh0, wc1.y);  fma2(x21[3], hh1, wc1.y);
        fma2(x20[4], hh0, ws0.x);  fma2(x21[4], hh1, ws0.x);
        fma2(x20[5], hh0, ws0.y);  fma2(x21[5], hh1, ws0.y);
        fma2(x20[6], hh0, ws1.x);  fma2(x21[6], hh1, ws1.x);
    }

    float z0[13], z1[13];
#pragma unroll
    for (int m = 0; m < 6; m++) {
        float2 v0 = unpack2(x20[m]);
        float2 v1 = unpack2(x21[m]);
        z0[2 * m] = v0.x; z0[2 * m + 1] = v0.y;
        z1[2 * m] = v1.x; z1[2 * m + 1] = v1.y;
    }
    z0[12] = unpack2(x20[6]).x;
    z1[12] = unpack2(x21[6]).x;

    epilogue(z0, d0, p0, out);
    epilogue(z1, d1, p1, out);
}

extern "C" void kernel_launch(void* const* d_in, const int* in_sizes, int n_in,
                              void* d_out, int out_size)
{
    const float* se  = (const float*)d_in[0];
    const float* te  = (const float*)d_in[1];
    const float* sr  = (const float*)d_in[2];
    const float* hc  = (const float*)d_in[3];
    const float* rot = (const float*)d_in[4];
    const float* w1  = (const float*)d_in[5];
    const float* b1  = (const float*)d_in[6];
    const float* w2  = (const float*)d_in[7];
    const float* b2  = (const float*)d_in[8];
    float* out = (float*)d_out;

    void *cw1p, *cw2p, *cb1p, *cb2p;
    cudaGetSymbolAddress(&cw1p, CW1);
    cudaGetSymbolAddress(&cw2p, CW2);
    cudaGetSymbolAddress(&cb1p, CB1);
    cudaGetSymbolAddress(&cb2p, CB2);

    prep_kernel<<<1, 256>>>(w1, b1, w2, b2,
                            (float*)cw1p, (float*)cw2p, (float*)cb1p, (float*)cb2p);
    energy_cnn_kernel<<<HALF / 256, 256>>>(se, te, sr, hc, rot, w1, w2, out);
}